// round 10
// baseline (speedup 1.0000x reference)
#include <cuda_runtime.h>
#include <cuda_fp16.h>
#include <math.h>
#include <float.h>

#define BATCH  8
#define NPT    1024
#define TOT    8388608        // BATCH*NPT*NPT
#define BLOCK  512
#define NWB    16             // warps per block
#define MAXG   152
#define MAXBLK 19
#define PARTN  (BATCH*MAXBLK*NPT)
#define DYNSM  65536          // 16 warps x 1024 floats staging buffer

// -------- persistent device state (reset each launch) ---------------------
__device__ __align__(16) __half g_Kh[TOT];        // K fp16 [b][i][j]
__device__ __align__(16) float  g_part[2][PARTN]; // double-buffered partials
__device__ int g_maxM[BATCH];
__device__ int g_bad;
__device__ int g_maxdiff[10];
__device__ unsigned g_batCnt[BATCH];
__device__ unsigned g_blkCnt;
__device__ unsigned g_hvyCount;                   // monotonic across launches
__device__ volatile unsigned g_hvyGen;

struct TagF { static constexpr bool value = false; };
struct TagT { static constexpr bool value = true;  };

__device__ __forceinline__ void heavy_barrier(int nb) {
    __threadfence();
    __syncthreads();
    if (threadIdx.x == 0) {
        unsigned g = g_hvyGen;
        unsigned t = atomicAdd(&g_hvyCount, 1u);
        if (t % (unsigned)nb == (unsigned)(nb - 1)) {
            __threadfence();
            g_hvyGen = g + 1u;
        } else {
            while (g_hvyGen == g) {}
        }
    }
    __syncthreads();
}

__device__ __forceinline__ void rel_inc(unsigned* p) {
    asm volatile("red.release.gpu.global.add.u32 [%0], %1;"
                 :: "l"(p), "r"(1u) : "memory");
}
__device__ __forceinline__ unsigned acq_ld(const unsigned* p) {
    unsigned v;
    asm volatile("ld.acquire.gpu.global.u32 %0, [%1];"
                 : "=r"(v) : "l"(p) : "memory");
    return v;
}
__device__ __forceinline__ int ld_cg_i(const int* p) {
    int v;
    asm volatile("ld.global.cg.b32 %0, [%1];" : "=r"(v) : "l"(p) : "memory");
    return v;
}
__device__ __forceinline__ float2 h2f(unsigned q) {
    __half2 h = *reinterpret_cast<__half2*>(&q);
    return __half22float2(h);
}
// warp-wide fp32 sum (butterfly; deterministic, uniform result in all lanes)
__device__ __forceinline__ float warp_sum(float x) {
#pragma unroll
    for (int o = 16; o; o >>= 1) x += __shfl_xor_sync(0xffffffffu, x, o);
    return x;
}

__global__ void __launch_bounds__(BLOCK, 1)
sot_kernel(const float* __restrict__ coord1, const float* __restrict__ prob1,
           const float* __restrict__ coord2, const float* __restrict__ prob2,
           float* __restrict__ Pout)
{
    extern __shared__ __align__(16) float s_dyn[];   // [16][1024] staging

    const int tid  = threadIdx.x;
    const int bid  = blockIdx.x;
    const int nb   = gridDim.x;
    const int lane = tid & 31;
    const int wid  = tid >> 5;

    const int myb  = (bid * BATCH) / nb;
    const int blk0 = (myb * nb + BATCH - 1) / BATCH;
    const int blk1 = ((myb + 1) * nb + BATCH - 1) / BATCH;
    const int nbb  = blk1 - blk0;
    const int lidx = bid - blk0;
    const int r_lo = (lidx * NPT) / nbb;
    const int r_hi = ((lidx + 1) * NPT) / nbb;
    const int nr   = r_hi - r_lo;

    __shared__ __align__(16) float s_v[2][NPT];
    __shared__ float s_u[2][64];
    __shared__ __align__(16) float s_b[NPT];
    __shared__ float s_a[64];
    __shared__ float2 s_xi[64];
    __shared__ float s_red[NWB];
    __shared__ float s_suma, s_sumb;
    __shared__ int   s_bad, s_f0, s_f1;

    __half* Kbh = g_Kh + ((size_t)myb << 20);

    // ---------------- resets ----------------------------------------------
    if (tid == 0) s_bad = 0;
    if (bid == 0) {
        if (tid == 1)               g_blkCnt = 0;
        if (tid == 2)               g_bad = 0;
        if (tid >= 8  && tid < 16)  g_batCnt[tid - 8] = 0;
        if (tid >= 16 && tid < 26)  g_maxdiff[tid - 16] = 0;
        if (tid >= 32 && tid < 40)  g_maxM[tid - 32] = 0;
    }

    // ---------------- block-local prob sums, a, b, coords -----------------
    const float*  p1b  = prob1 + (myb << 10);
    const float2* p2b2 = (const float2*)(prob2 + (myb << 10));
    {
        const float2* p1b2 = (const float2*)p1b;
        float2 x1 = p1b2[tid];
        float2 x2 = p2b2[tid];
        float sa = (x1.x + 1e-8f) + (x1.y + 1e-8f);
        float sb = (x2.x + 1e-8f) + (x2.y + 1e-8f);
#pragma unroll
        for (int o = 16; o; o >>= 1) {
            sa += __shfl_xor_sync(0xffffffffu, sa, o);
            sb += __shfl_xor_sync(0xffffffffu, sb, o);
        }
        if (lane == 0) s_red[wid] = sa;
        __syncthreads();
        if (wid == 0) {
            float t = (lane < NWB) ? s_red[lane] : 0.f;
#pragma unroll
            for (int o = 16; o; o >>= 1) t += __shfl_xor_sync(0xffffffffu, t, o);
            if (lane == 0) s_suma = t;
        }
        __syncthreads();
        if (lane == 0) s_red[wid] = sb;
        __syncthreads();
        if (wid == 0) {
            float t = (lane < NWB) ? s_red[lane] : 0.f;
#pragma unroll
            for (int o = 16; o; o >>= 1) t += __shfl_xor_sync(0xffffffffu, t, o);
            if (lane == 0) s_sumb = t;
        }
        __syncthreads();
    }
    {
        float2 x2 = p2b2[tid];
        ((float2*)s_b)[tid] = make_float2((x2.x + 1e-8f) / s_sumb,
                                          (x2.y + 1e-8f) / s_sumb);
        if (tid < nr) {
            s_a[tid]  = (p1b[r_lo + tid] + 1e-8f) / s_suma;
            s_xi[tid] = ((const float2*)(coord1 + (myb << 11)))[r_lo + tid];
        }
        ((float2*)s_v[1])[tid] = make_float2(1.0f/1024.0f, 1.0f/1024.0f);
        if (tid < 64) s_u[1][tid] = 1.0f/1024.0f;
    }
    heavy_barrier(nb);

    // ---------------- light barriers ---------------------------------------
    unsigned phB = 0, phG = 0;
    auto batch_bar = [&]() {
        phB++;
        __syncthreads();
        if (tid == 0) {
            rel_inc(&g_batCnt[myb]);
            while (acq_ld(&g_batCnt[myb]) < phB * (unsigned)nbb) {}
        }
        __syncthreads();
    };
    auto global_bar = [&]() {
        phG++;
        __syncthreads();
        if (tid == 0) {
            if (s_bad) { atomicOr(&g_bad, 1); s_bad = 0; }
            rel_inc(&g_blkCnt);
            while (acq_ld(&g_blkCnt) < phG * (unsigned)nb) {}
        }
        __syncthreads();
    };

    // ---------------- maxM over own rows ----------------------------------
    {
        const float2* cy = (const float2*)(coord2 + (myb << 11));
        float m = 0.f;
        for (int r = wid; r < nr; r += NWB) {
            float2 xi = s_xi[r];
            for (int j = lane; j < NPT; j += 32) {
                float2 yy = cy[j];
                float d0 = xi.x - yy.x, d1 = xi.y - yy.y;
                m = fmaxf(m, d0 * d0 + d1 * d1);
            }
        }
#pragma unroll
        for (int o = 16; o; o >>= 1) m = fmaxf(m, __shfl_xor_sync(0xffffffffu, m, o));
        if (lane == 0) s_red[wid] = m;
        __syncthreads();
        if (wid == 0) {
            float t = (lane < NWB) ? s_red[lane] : 0.f;
#pragma unroll
            for (int o = 16; o; o >>= 1) t = fmaxf(t, __shfl_xor_sync(0xffffffffu, t, o));
            if (lane == 0 && tid == 0) atomicMax(&g_maxM[myb], __float_as_int(t));
        }
    }
    batch_bar();

    // ---------------- K materialization (fp16) + initial partials ----------
    {
        float nscale = -10.0f / __int_as_float(ld_cg_i(&g_maxM[myb]));
        const float4* cy4 = (const float4*)(coord2 + (myb << 11));
        float4 yy = cy4[tid];                 // cols 2tid, 2tid+1
        float2 acc = make_float2(0.f, 0.f);
        __half2* Krow = (__half2*)(Kbh + ((size_t)r_lo << 10)) + tid;
        for (int r = 0; r < nr; ++r) {
            float2 xi = s_xi[r];
            float d0 = xi.x - yy.x, d1 = xi.y - yy.y;
            float d2 = xi.x - yy.z, d3 = xi.y - yy.w;
            float kx = __expf((d0 * d0 + d1 * d1) * nscale);
            float ky = __expf((d2 * d2 + d3 * d3) * nscale);
            __half2 h = __floats2half2_rn(kx, ky);
            Krow[(size_t)r << 9] = h;
            float2 f = __half22float2(h);     // rounded values for consistency
            acc.x += f.x; acc.y += f.y;
        }
        float2* pm0 = (float2*)(g_part[0] + ((myb * MAXBLK + lidx) << 10));
        pm0[tid] = make_float2(acc.x * (1.0f/1024.0f), acc.y * (1.0f/1024.0f));
    }

    // ---------------- final output ----------------------------------------
    auto write_final = [&](int buf) {
        const float4* v4 = (const float4*)s_v[buf];
        for (int r = wid; r < nr; r += NWB) {
            float u = s_u[buf][r];
            const uint2* k2 = (const uint2*)(Kbh + ((size_t)(r_lo + r) << 10));
            float4* o4 = (float4*)(Pout + ((size_t)myb << 20) + ((size_t)(r_lo + r) << 10));
#pragma unroll
            for (int c = 0; c < 8; ++c) {
                uint2 q = __ldg(k2 + lane + 32 * c);
                float2 f0 = h2f(q.x), f1 = h2f(q.y);
                float4 vv = v4[lane + 32 * c];
                float4 pn;
                pn.x = (u * f0.x) * vv.x;  pn.y = (u * f0.y) * vv.y;
                pn.z = (u * f1.x) * vv.z;  pn.w = (u * f1.y) * vv.w;
                __stcs(o4 + lane + 32 * c, pn);
            }
        }
    };

    // ---------------- fused u-pass + partials (+ chunk-diff on LAST) -------
    int parity = 0;
    auto fused = [&](auto LASTC, int cp) -> float {
        constexpr bool LAST = decltype(LASTC)::value;
        const float4* v4  = (const float4*)s_v[cp];
        const float4* v4p = (const float4*)s_v[cp ^ 1];
        float lm = 0.f;
        float racc[32];
#pragma unroll
        for (int i = 0; i < 32; ++i) racc[i] = 0.f;
        for (int r = wid; r < nr; r += NWB) {
            const uint2* m2 = (const uint2*)(Kbh + ((size_t)(r_lo + r) << 10));
            float kf[32];
            float d0 = 0.f, d1 = 0.f;
#pragma unroll
            for (int cch = 0; cch < 8; ++cch) {
                uint2 q = __ldg(m2 + lane + 32 * cch);
                float2 fa = h2f(q.x), fb = h2f(q.y);
                kf[4*cch]   = fa.x;  kf[4*cch+1] = fa.y;
                kf[4*cch+2] = fb.x;  kf[4*cch+3] = fb.y;
                float4 vv = v4[lane + 32 * cch];
                d0 = fmaf(fa.x, vv.x, fmaf(fa.y, vv.y, d0));
                d1 = fmaf(fb.x, vv.z, fmaf(fb.y, vv.w, d1));
            }
            float dot = warp_sum(d0 + d1);       // uniform across warp
            float uu = s_a[r] / dot;
            if (lane == 0) {
                if (dot == 0.f || !(fabsf(uu) <= FLT_MAX)) s_bad = 1;
                s_u[cp][r] = uu;
            }
#pragma unroll
            for (int i = 0; i < 32; ++i)
                racc[i] = fmaf(kf[i], uu, racc[i]);
            if (LAST) {                          // fused chunk-diff vs prev gen
                float up = s_u[cp ^ 1][r];
#pragma unroll
                for (int cch = 0; cch < 8; ++cch) {
                    float4 vv = v4 [lane + 32 * cch];
                    float4 vp = v4p[lane + 32 * cch];
                    float x0 = fabsf((uu * kf[4*cch  ]) * vv.x - (up * kf[4*cch  ]) * vp.x);
                    float x1 = fabsf((uu * kf[4*cch+1]) * vv.y - (up * kf[4*cch+1]) * vp.y);
                    float x2 = fabsf((uu * kf[4*cch+2]) * vv.z - (up * kf[4*cch+2]) * vp.z);
                    float x3 = fabsf((uu * kf[4*cch+3]) * vv.w - (up * kf[4*cch+3]) * vp.w);
                    lm = fmaxf(lm, fmaxf(fmaxf(x0, x1), fmaxf(x2, x3)));
                }
            }
        }
        // stage per-warp partials (cols 4*(lane+32*cch)+0..3)
        float4* buf4 = (float4*)(s_dyn + (wid << 10));
#pragma unroll
        for (int cch = 0; cch < 8; ++cch)
            buf4[lane + 32 * cch] = make_float4(racc[4*cch], racc[4*cch+1],
                                                racc[4*cch+2], racc[4*cch+3]);
        __syncthreads();
        // deterministic 16-way cross-warp reduction, cols 2tid,2tid+1
        float2 sum = make_float2(0.f, 0.f);
#pragma unroll
        for (int w = 0; w < NWB; ++w) {
            float2 x = ((const float2*)(s_dyn + (w << 10)))[tid];
            sum.x += x.x; sum.y += x.y;
        }
        float2* pd = (float2*)(g_part[parity ^ 1] + ((myb * MAXBLK + lidx) << 10));
        pd[tid] = sum;
        return lm;
    };

    // ---------------- Sinkhorn chunks --------------------------------------
    for (int c = 0; c < 10; ++c) {
        const int cp = c & 1;
        float lm = 0.f;
        for (int it = 0; it < 10; ++it) {
            batch_bar();
            // ---- B: v = b / sum_of_partials ------------------------------
            {
                const float2* pb = (const float2*)(g_part[parity] + ((myb * MAXBLK) << 10));
                float2 kt = make_float2(0.f, 0.f);
                if (nbb == 19) {
#pragma unroll
                    for (int p = 0; p < 19; ++p) {
                        float2 x = __ldcg(pb + (p << 9) + tid);
                        kt.x += x.x; kt.y += x.y;
                    }
                } else {
                    for (int p = 0; p < nbb; ++p) {
                        float2 x = __ldcg(pb + (p << 9) + tid);
                        kt.x += x.x; kt.y += x.y;
                    }
                }
                float2 bb = ((const float2*)s_b)[tid];
                float vx = bb.x / kt.x;
                float vy = bb.y / kt.y;
                if (kt.x == 0.f || kt.y == 0.f ||
                    !(fabsf(vx) <= FLT_MAX) || !(fabsf(vy) <= FLT_MAX))
                    s_bad = 1;
                ((float2*)s_v[cp])[tid] = make_float2(vx, vy);
            }
            __syncthreads();
            if (it < 9) fused(TagF{}, cp);
            else        lm = fused(TagT{}, cp);
            parity ^= 1;
        }

        // ---- chunk decision: reduce lm, consensus, act --------------------
#pragma unroll
        for (int o = 16; o; o >>= 1) lm = fmaxf(lm, __shfl_xor_sync(0xffffffffu, lm, o));
        if (lane == 0) s_red[wid] = lm;
        __syncthreads();
        if (wid == 0) {
            float t = (lane < NWB) ? s_red[lane] : 0.f;
#pragma unroll
            for (int o = 16; o; o >>= 1) t = fmaxf(t, __shfl_xor_sync(0xffffffffu, t, o));
            if (lane == 0 && tid == 0) atomicMax(&g_maxdiff[c], __float_as_int(t));
        }
        global_bar();                      // tid0's release orders its atomics
        if (tid == 0) {
            s_f0 = ld_cg_i(&g_bad);
            s_f1 = ld_cg_i(&g_maxdiff[c]);
        }
        __syncthreads();
        if (s_f0) {                        // bad: previous chunk's P (or P0)
            write_final(cp ^ 1);
            return;
        }
        if (__int_as_float(s_f1) < 1e-3f || c == 9) {
            write_final(cp);
            return;
        }
    }
}

extern "C" void kernel_launch(void* const* d_in, const int* in_sizes, int n_in,
                              void* d_out, int out_size) {
    static int nsm = 0;
    if (nsm == 0) {
        int dev = 0; cudaGetDevice(&dev);
        int v = 0;
        if (cudaDeviceGetAttribute(&v, cudaDevAttrMultiProcessorCount, dev)
                != cudaSuccess || v <= 0) v = 148;
        if (v > MAXG) v = MAXG;
        if (v < BATCH) v = BATCH;
        nsm = v;
    }
    // opt-in to 64KB dynamic smem (idempotent host-side call, capture-safe)
    cudaFuncSetAttribute(sot_kernel, cudaFuncAttributeMaxDynamicSharedMemorySize,
                         DYNSM);
    const float* c1 = nullptr; const float* p1 = nullptr;
    const float* c2 = nullptr; const float* p2 = nullptr;
    for (int i = 0; i < n_in; ++i) {
        if (in_sizes[i] == BATCH * NPT * 2) {
            if (!c1) c1 = (const float*)d_in[i]; else c2 = (const float*)d_in[i];
        } else if (in_sizes[i] == BATCH * NPT) {
            if (!p1) p1 = (const float*)d_in[i]; else p2 = (const float*)d_in[i];
        }
    }
    sot_kernel<<<nsm, BLOCK, DYNSM>>>(c1, p1, c2, p2, (float*)d_out);
}

// round 11
// speedup vs baseline: 1.0292x; 1.0292x over previous
#include <cuda_runtime.h>
#include <cuda_fp16.h>
#include <math.h>
#include <float.h>

#define BATCH  8
#define NPT    1024
#define TOT    8388608        // BATCH*NPT*NPT
#define BLOCK  512
#define NWB    16             // warps per block
#define MAXG   152
#define MAXBLK 19
#define PARTN  (BATCH*MAXBLK*NPT)
#define DYNSM  65536          // 16 warps x 1024 floats staging buffer

// -------- persistent device state (reset each launch) ---------------------
__device__ __align__(16) __half g_Kh[TOT];        // K fp16 [b][i][j]
__device__ __align__(16) float  g_part[2][PARTN]; // double-buffered partials
__device__ int g_maxM[BATCH];
__device__ int g_bad;
__device__ int g_maxdiff[10];
__device__ unsigned g_batCnt[BATCH];
__device__ unsigned g_blkCnt;
__device__ unsigned g_hvyCount;                   // monotonic across launches
__device__ volatile unsigned g_hvyGen;

struct TagF { static constexpr bool value = false; };
struct TagT { static constexpr bool value = true;  };

__device__ __forceinline__ void heavy_barrier(int nb) {
    __threadfence();
    __syncthreads();
    if (threadIdx.x == 0) {
        unsigned g = g_hvyGen;
        unsigned t = atomicAdd(&g_hvyCount, 1u);
        if (t % (unsigned)nb == (unsigned)(nb - 1)) {
            __threadfence();
            g_hvyGen = g + 1u;
        } else {
            while (g_hvyGen == g) {}
        }
    }
    __syncthreads();
}

__device__ __forceinline__ void rel_inc(unsigned* p) {
    asm volatile("red.release.gpu.global.add.u32 [%0], %1;"
                 :: "l"(p), "r"(1u) : "memory");
}
__device__ __forceinline__ unsigned acq_ld(const unsigned* p) {
    unsigned v;
    asm volatile("ld.acquire.gpu.global.u32 %0, [%1];"
                 : "=r"(v) : "l"(p) : "memory");
    return v;
}
__device__ __forceinline__ int ld_cg_i(const int* p) {
    int v;
    asm volatile("ld.global.cg.b32 %0, [%1];" : "=r"(v) : "l"(p) : "memory");
    return v;
}
__device__ __forceinline__ float2 h2f(unsigned q) {
    __half2 h = *reinterpret_cast<__half2*>(&q);
    return __half22float2(h);
}
// warp-wide fp32 sum (butterfly; deterministic, uniform result in all lanes)
__device__ __forceinline__ float warp_sum(float x) {
#pragma unroll
    for (int o = 16; o; o >>= 1) x += __shfl_xor_sync(0xffffffffu, x, o);
    return x;
}

__global__ void __launch_bounds__(BLOCK, 1)
sot_kernel(const float* __restrict__ coord1, const float* __restrict__ prob1,
           const float* __restrict__ coord2, const float* __restrict__ prob2,
           float* __restrict__ Pout)
{
    extern __shared__ __align__(16) float s_dyn[];   // [16][1024] staging

    const int tid  = threadIdx.x;
    const int bid  = blockIdx.x;
    const int nb   = gridDim.x;
    const int lane = tid & 31;
    const int wid  = tid >> 5;

    const int myb  = (bid * BATCH) / nb;
    const int blk0 = (myb * nb + BATCH - 1) / BATCH;
    const int blk1 = ((myb + 1) * nb + BATCH - 1) / BATCH;
    const int nbb  = blk1 - blk0;
    const int lidx = bid - blk0;
    const int r_lo = (lidx * NPT) / nbb;
    const int r_hi = ((lidx + 1) * NPT) / nbb;
    const int nr   = r_hi - r_lo;

    __shared__ __align__(16) float s_v[2][NPT];
    __shared__ float s_u[2][64];
    __shared__ __align__(16) float s_b[NPT];
    __shared__ float s_a[64];
    __shared__ float2 s_xi[64];
    __shared__ float s_red[NWB];
    __shared__ float s_suma, s_sumb;
    __shared__ int   s_bad, s_f0, s_f1;

    __half* Kbh = g_Kh + ((size_t)myb << 20);

    // ---------------- resets ----------------------------------------------
    if (tid == 0) s_bad = 0;
    if (bid == 0) {
        if (tid == 1)               g_blkCnt = 0;
        if (tid == 2)               g_bad = 0;
        if (tid >= 8  && tid < 16)  g_batCnt[tid - 8] = 0;
        if (tid >= 16 && tid < 26)  g_maxdiff[tid - 16] = 0;
        if (tid >= 32 && tid < 40)  g_maxM[tid - 32] = 0;
    }

    // ---------------- block-local prob sums, a, b, coords -----------------
    const float*  p1b  = prob1 + (myb << 10);
    const float2* p2b2 = (const float2*)(prob2 + (myb << 10));
    {
        const float2* p1b2 = (const float2*)p1b;
        float2 x1 = p1b2[tid];
        float2 x2 = p2b2[tid];
        float sa = (x1.x + 1e-8f) + (x1.y + 1e-8f);
        float sb = (x2.x + 1e-8f) + (x2.y + 1e-8f);
#pragma unroll
        for (int o = 16; o; o >>= 1) {
            sa += __shfl_xor_sync(0xffffffffu, sa, o);
            sb += __shfl_xor_sync(0xffffffffu, sb, o);
        }
        if (lane == 0) s_red[wid] = sa;
        __syncthreads();
        if (wid == 0) {
            float t = (lane < NWB) ? s_red[lane] : 0.f;
#pragma unroll
            for (int o = 16; o; o >>= 1) t += __shfl_xor_sync(0xffffffffu, t, o);
            if (lane == 0) s_suma = t;
        }
        __syncthreads();
        if (lane == 0) s_red[wid] = sb;
        __syncthreads();
        if (wid == 0) {
            float t = (lane < NWB) ? s_red[lane] : 0.f;
#pragma unroll
            for (int o = 16; o; o >>= 1) t += __shfl_xor_sync(0xffffffffu, t, o);
            if (lane == 0) s_sumb = t;
        }
        __syncthreads();
    }
    {
        float2 x2 = p2b2[tid];
        ((float2*)s_b)[tid] = make_float2((x2.x + 1e-8f) / s_sumb,
                                          (x2.y + 1e-8f) / s_sumb);
        if (tid < nr) {
            s_a[tid]  = (p1b[r_lo + tid] + 1e-8f) / s_suma;
            s_xi[tid] = ((const float2*)(coord1 + (myb << 11)))[r_lo + tid];
        }
        ((float2*)s_v[1])[tid] = make_float2(1.0f/1024.0f, 1.0f/1024.0f);
        if (tid < 64) s_u[1][tid] = 1.0f/1024.0f;
    }
    heavy_barrier(nb);

    // ---------------- light barriers ---------------------------------------
    unsigned phB = 0, phG = 0;
    auto batch_bar = [&]() {
        phB++;
        __syncthreads();
        if (tid == 0) {
            rel_inc(&g_batCnt[myb]);
            while (acq_ld(&g_batCnt[myb]) < phB * (unsigned)nbb) {}
        }
        __syncthreads();
    };
    auto global_bar = [&]() {
        phG++;
        __syncthreads();
        if (tid == 0) {
            if (s_bad) { atomicOr(&g_bad, 1); s_bad = 0; }
            rel_inc(&g_blkCnt);
            while (acq_ld(&g_blkCnt) < phG * (unsigned)nb) {}
        }
        __syncthreads();
    };

    // ---------------- maxM over own rows ----------------------------------
    {
        const float2* cy = (const float2*)(coord2 + (myb << 11));
        float m = 0.f;
        for (int r = wid; r < nr; r += NWB) {
            float2 xi = s_xi[r];
            for (int j = lane; j < NPT; j += 32) {
                float2 yy = cy[j];
                float d0 = xi.x - yy.x, d1 = xi.y - yy.y;
                m = fmaxf(m, d0 * d0 + d1 * d1);
            }
        }
#pragma unroll
        for (int o = 16; o; o >>= 1) m = fmaxf(m, __shfl_xor_sync(0xffffffffu, m, o));
        if (lane == 0) s_red[wid] = m;
        __syncthreads();
        if (wid == 0) {
            float t = (lane < NWB) ? s_red[lane] : 0.f;
#pragma unroll
            for (int o = 16; o; o >>= 1) t = fmaxf(t, __shfl_xor_sync(0xffffffffu, t, o));
            if (lane == 0 && tid == 0) atomicMax(&g_maxM[myb], __float_as_int(t));
        }
    }
    batch_bar();

    // ---------------- K materialization (fp16) + initial partials ----------
    {
        float nscale = -10.0f / __int_as_float(ld_cg_i(&g_maxM[myb]));
        const float4* cy4 = (const float4*)(coord2 + (myb << 11));
        float4 yy = cy4[tid];                 // cols 2tid, 2tid+1
        float2 acc = make_float2(0.f, 0.f);
        __half2* Krow = (__half2*)(Kbh + ((size_t)r_lo << 10)) + tid;
        for (int r = 0; r < nr; ++r) {
            float2 xi = s_xi[r];
            float d0 = xi.x - yy.x, d1 = xi.y - yy.y;
            float d2 = xi.x - yy.z, d3 = xi.y - yy.w;
            float kx = __expf((d0 * d0 + d1 * d1) * nscale);
            float ky = __expf((d2 * d2 + d3 * d3) * nscale);
            __half2 h = __floats2half2_rn(kx, ky);
            Krow[(size_t)r << 9] = h;
            float2 f = __half22float2(h);     // rounded values for consistency
            acc.x += f.x; acc.y += f.y;
        }
        float2* pm0 = (float2*)(g_part[0] + ((myb * MAXBLK + lidx) << 10));
        pm0[tid] = make_float2(acc.x * (1.0f/1024.0f), acc.y * (1.0f/1024.0f));
    }

    // ---------------- final output ----------------------------------------
    auto write_final = [&](int buf) {
        const float4* v4 = (const float4*)s_v[buf];
        for (int r = wid; r < nr; r += NWB) {
            float u = s_u[buf][r];
            const uint2* k2 = (const uint2*)(Kbh + ((size_t)(r_lo + r) << 10));
            float4* o4 = (float4*)(Pout + ((size_t)myb << 20) + ((size_t)(r_lo + r) << 10));
#pragma unroll
            for (int c = 0; c < 8; ++c) {
                uint2 q = __ldg(k2 + lane + 32 * c);
                float2 f0 = h2f(q.x), f1 = h2f(q.y);
                float4 vv = v4[lane + 32 * c];
                float4 pn;
                pn.x = (u * f0.x) * vv.x;  pn.y = (u * f0.y) * vv.y;
                pn.z = (u * f1.x) * vv.z;  pn.w = (u * f1.y) * vv.w;
                __stcs(o4 + lane + 32 * c, pn);
            }
        }
    };

    // ---------------- fused u-pass + partials (+ chunk-diff on LAST) -------
    // Row pairs (r, r+16) processed concurrently: two independent
    // load->dot->shuffle chains in flight; K reloaded (L1 hit) for the
    // accumulate phase so no register WAR serializes consecutive rows.
    int parity = 0;
    auto fused = [&](auto LASTC, int cp) -> float {
        constexpr bool LAST = decltype(LASTC)::value;
        const float4* v4  = (const float4*)s_v[cp];
        const float4* v4p = (const float4*)s_v[cp ^ 1];
        float lm = 0.f;
        float racc[32];
#pragma unroll
        for (int i = 0; i < 32; ++i) racc[i] = 0.f;
        for (int r0 = wid; r0 < nr; r0 += 2 * NWB) {
            const int r1 = r0 + NWB;
            const bool two = (r1 < nr);
            const uint2* mA = (const uint2*)(Kbh + ((size_t)(r_lo + r0) << 10));
            const uint2* mB = two ? (const uint2*)(Kbh + ((size_t)(r_lo + r1) << 10))
                                  : mA;
            // ---- dot phase: 4 chains per row, both rows in flight ---------
            float a0 = 0.f, a1 = 0.f, a2 = 0.f, a3 = 0.f;
            float b0 = 0.f, b1 = 0.f, b2 = 0.f, b3 = 0.f;
#pragma unroll
            for (int cch = 0; cch < 8; cch += 2) {
                uint2 qA0 = __ldg(mA + lane + 32 * cch);
                uint2 qA1 = __ldg(mA + lane + 32 * (cch + 1));
                uint2 qB0 = __ldg(mB + lane + 32 * cch);
                uint2 qB1 = __ldg(mB + lane + 32 * (cch + 1));
                float4 vv0 = v4[lane + 32 * cch];
                float4 vv1 = v4[lane + 32 * (cch + 1)];
                float2 f;
                f = h2f(qA0.x); a0 = fmaf(f.x, vv0.x, fmaf(f.y, vv0.y, a0));
                f = h2f(qA0.y); a1 = fmaf(f.x, vv0.z, fmaf(f.y, vv0.w, a1));
                f = h2f(qA1.x); a2 = fmaf(f.x, vv1.x, fmaf(f.y, vv1.y, a2));
                f = h2f(qA1.y); a3 = fmaf(f.x, vv1.z, fmaf(f.y, vv1.w, a3));
                f = h2f(qB0.x); b0 = fmaf(f.x, vv0.x, fmaf(f.y, vv0.y, b0));
                f = h2f(qB0.y); b1 = fmaf(f.x, vv0.z, fmaf(f.y, vv0.w, b1));
                f = h2f(qB1.x); b2 = fmaf(f.x, vv1.x, fmaf(f.y, vv1.y, b2));
                f = h2f(qB1.y); b3 = fmaf(f.x, vv1.z, fmaf(f.y, vv1.w, b3));
            }
            float dA = warp_sum((a0 + a1) + (a2 + a3));
            float dB = warp_sum((b0 + b1) + (b2 + b3));
            float uA = __fdividef(s_a[r0], dA);
            float uB = two ? __fdividef(s_a[r1], dB) : 0.f;
            if (lane == 0) {
                if (dA == 0.f || !(fabsf(uA) <= FLT_MAX)) s_bad = 1;
                s_u[cp][r0] = uA;
                if (two) {
                    if (dB == 0.f || !(fabsf(uB) <= FLT_MAX)) s_bad = 1;
                    s_u[cp][r1] = uB;
                }
            }
            float upA = 0.f, upB = 0.f;
            if (LAST) { upA = s_u[cp ^ 1][r0]; upB = two ? s_u[cp ^ 1][r1] : 0.f; }
            // ---- accumulate phase: reload K (L1 hit), no kf registers -----
#pragma unroll
            for (int cch = 0; cch < 8; ++cch) {
                uint2 qA = __ldg(mA + lane + 32 * cch);
                uint2 qB = __ldg(mB + lane + 32 * cch);
                float2 fa = h2f(qA.x), fb = h2f(qA.y);
                float2 ga = h2f(qB.x), gb = h2f(qB.y);
                racc[4*cch]   = fmaf(fa.x, uA, racc[4*cch]);
                racc[4*cch+1] = fmaf(fa.y, uA, racc[4*cch+1]);
                racc[4*cch+2] = fmaf(fb.x, uA, racc[4*cch+2]);
                racc[4*cch+3] = fmaf(fb.y, uA, racc[4*cch+3]);
                racc[4*cch]   = fmaf(ga.x, uB, racc[4*cch]);
                racc[4*cch+1] = fmaf(ga.y, uB, racc[4*cch+1]);
                racc[4*cch+2] = fmaf(gb.x, uB, racc[4*cch+2]);
                racc[4*cch+3] = fmaf(gb.y, uB, racc[4*cch+3]);
                if (LAST) {                      // fused chunk-diff, both rows
                    float4 vv = v4 [lane + 32 * cch];
                    float4 vp = v4p[lane + 32 * cch];
                    float x0 = fabsf((uA * fa.x) * vv.x - (upA * fa.x) * vp.x);
                    float x1 = fabsf((uA * fa.y) * vv.y - (upA * fa.y) * vp.y);
                    float x2 = fabsf((uA * fb.x) * vv.z - (upA * fb.x) * vp.z);
                    float x3 = fabsf((uA * fb.y) * vv.w - (upA * fb.y) * vp.w);
                    lm = fmaxf(lm, fmaxf(fmaxf(x0, x1), fmaxf(x2, x3)));
                    float y0 = fabsf((uB * ga.x) * vv.x - (upB * ga.x) * vp.x);
                    float y1 = fabsf((uB * ga.y) * vv.y - (upB * ga.y) * vp.y);
                    float y2 = fabsf((uB * gb.x) * vv.z - (upB * gb.x) * vp.z);
                    float y3 = fabsf((uB * gb.y) * vv.w - (upB * gb.y) * vp.w);
                    lm = fmaxf(lm, fmaxf(fmaxf(y0, y1), fmaxf(y2, y3)));
                }
            }
        }
        // stage per-warp partials (cols 4*(lane+32*cch)+0..3)
        float4* buf4 = (float4*)(s_dyn + (wid << 10));
#pragma unroll
        for (int cch = 0; cch < 8; ++cch)
            buf4[lane + 32 * cch] = make_float4(racc[4*cch], racc[4*cch+1],
                                                racc[4*cch+2], racc[4*cch+3]);
        __syncthreads();
        // deterministic 16-way cross-warp reduction, cols 2tid,2tid+1
        float2 sum = make_float2(0.f, 0.f);
#pragma unroll
        for (int w = 0; w < NWB; ++w) {
            float2 x = ((const float2*)(s_dyn + (w << 10)))[tid];
            sum.x += x.x; sum.y += x.y;
        }
        float2* pd = (float2*)(g_part[parity ^ 1] + ((myb * MAXBLK + lidx) << 10));
        pd[tid] = sum;
        return lm;
    };

    // ---------------- Sinkhorn chunks --------------------------------------
    for (int c = 0; c < 10; ++c) {
        const int cp = c & 1;
        float lm = 0.f;
        for (int it = 0; it < 10; ++it) {
            batch_bar();
            // ---- B: v = b / sum_of_partials ------------------------------
            {
                const float2* pb = (const float2*)(g_part[parity] + ((myb * MAXBLK) << 10));
                float2 kt = make_float2(0.f, 0.f);
                if (nbb == 19) {
#pragma unroll
                    for (int p = 0; p < 19; ++p) {
                        float2 x = __ldcg(pb + (p << 9) + tid);
                        kt.x += x.x; kt.y += x.y;
                    }
                } else {
                    for (int p = 0; p < nbb; ++p) {
                        float2 x = __ldcg(pb + (p << 9) + tid);
                        kt.x += x.x; kt.y += x.y;
                    }
                }
                float2 bb = ((const float2*)s_b)[tid];
                float vx = __fdividef(bb.x, kt.x);
                float vy = __fdividef(bb.y, kt.y);
                if (kt.x == 0.f || kt.y == 0.f ||
                    !(fabsf(vx) <= FLT_MAX) || !(fabsf(vy) <= FLT_MAX))
                    s_bad = 1;
                ((float2*)s_v[cp])[tid] = make_float2(vx, vy);
            }
            __syncthreads();
            if (it < 9) fused(TagF{}, cp);
            else        lm = fused(TagT{}, cp);
            parity ^= 1;
        }

        // ---- chunk decision: reduce lm, consensus, act --------------------
#pragma unroll
        for (int o = 16; o; o >>= 1) lm = fmaxf(lm, __shfl_xor_sync(0xffffffffu, lm, o));
        if (lane == 0) s_red[wid] = lm;
        __syncthreads();
        if (wid == 0) {
            float t = (lane < NWB) ? s_red[lane] : 0.f;
#pragma unroll
            for (int o = 16; o; o >>= 1) t = fmaxf(t, __shfl_xor_sync(0xffffffffu, t, o));
            if (lane == 0 && tid == 0) atomicMax(&g_maxdiff[c], __float_as_int(t));
        }
        global_bar();                      // tid0's release orders its atomics
        if (tid == 0) {
            s_f0 = ld_cg_i(&g_bad);
            s_f1 = ld_cg_i(&g_maxdiff[c]);
        }
        __syncthreads();
        if (s_f0) {                        // bad: previous chunk's P (or P0)
            write_final(cp ^ 1);
            return;
        }
        if (__int_as_float(s_f1) < 1e-3f || c == 9) {
            write_final(cp);
            return;
        }
    }
}

extern "C" void kernel_launch(void* const* d_in, const int* in_sizes, int n_in,
                              void* d_out, int out_size) {
    static int nsm = 0;
    if (nsm == 0) {
        int dev = 0; cudaGetDevice(&dev);
        int v = 0;
        if (cudaDeviceGetAttribute(&v, cudaDevAttrMultiProcessorCount, dev)
                != cudaSuccess || v <= 0) v = 148;
        if (v > MAXG) v = MAXG;
        if (v < BATCH) v = BATCH;
        nsm = v;
    }
    // opt-in to 64KB dynamic smem (idempotent host-side call, capture-safe)
    cudaFuncSetAttribute(sot_kernel, cudaFuncAttributeMaxDynamicSharedMemorySize,
                         DYNSM);
    const float* c1 = nullptr; const float* p1 = nullptr;
    const float* c2 = nullptr; const float* p2 = nullptr;
    for (int i = 0; i < n_in; ++i) {
        if (in_sizes[i] == BATCH * NPT * 2) {
            if (!c1) c1 = (const float*)d_in[i]; else c2 = (const float*)d_in[i];
        } else if (in_sizes[i] == BATCH * NPT) {
            if (!p1) p1 = (const float*)d_in[i]; else p2 = (const float*)d_in[i];
        }
    }
    sot_kernel<<<nsm, BLOCK, DYNSM>>>(c1, p1, c2, p2, (float*)d_out);
}